// round 1
// baseline (speedup 1.0000x reference)
#include <cuda_runtime.h>

// Deform_Conv_V1: fused offset-conv + deformable conv + ReLU.
// B=8, Cin=32, H=W=160, Cout=32, K=3, PAD=1.
// Inputs (metadata order): x (8,32,160,160), w_off (18,32,3,3), b_off (18,), w_dcn (32,32,3,3)
// Output: (8,32,160,160) fp32.

#define Hn  160
#define Wn  160
#define CIN 32
#define COUT 32
#define HWs (Hn * Wn)

__global__ __launch_bounds__(256, 2)
void dcn_fused_kernel(const float* __restrict__ x,
                      const float* __restrict__ w_off,
                      const float* __restrict__ b_off,
                      const float* __restrict__ w_dcn,
                      float* __restrict__ out)
{
    extern __shared__ float smem[];
    float* w_dcn_s = smem;               // [9][32][32]  (k, c, o) — 9216 floats
    float* w_off_s = smem + 9 * 32 * 32; // [9][32][18]  (k, c, oc) — 5184 floats

    const int tid = threadIdx.x;

    // Transposed weight staging: global w_dcn is (o, c, ky, kx) row-major.
    for (int i = tid; i < 9 * 32 * 32; i += 256) {
        int k = i >> 10;
        int r = i & 1023;
        int c = r >> 5;
        int o = r & 31;
        w_dcn_s[i] = w_dcn[o * 288 + c * 9 + k];
    }
    // Global w_off is (oc, c, ky, kx) row-major, oc in [0,18).
    for (int i = tid; i < 9 * 32 * 18; i += 256) {
        int k = i / 576;
        int r = i - k * 576;
        int c = r / 18;
        int oc = r - c * 18;
        w_off_s[i] = w_off[oc * 288 + c * 9 + k];
    }
    __syncthreads();

    const int pix = blockIdx.x * 256 + tid;           // 0 .. 204799
    const int b  = pix / HWs;
    const int hw = pix - b * HWs;
    const int h  = hw / Wn;
    const int w  = hw - h * Wn;
    const float* xb = x + (size_t)b * CIN * HWs;

    // ---------------- Stage 1: offset conv (18 channels in registers) ----------------
    float offs[18];
#pragma unroll
    for (int j = 0; j < 18; j++) offs[j] = __ldg(&b_off[j]);

#pragma unroll 1
    for (int k = 0; k < 9; k++) {
        const int ky = k / 3;
        const int kx = k - 3 * ky;
        const int yy = h - 1 + ky;
        const int xx = w - 1 + kx;
        if (yy >= 0 && yy < Hn && xx >= 0 && xx < Wn) {
            const float* xp = xb + yy * Wn + xx;
            const float2* wp = (const float2*)(w_off_s + k * 32 * 18);
#pragma unroll 4
            for (int c = 0; c < CIN; c++) {
                const float xv = __ldg(xp + c * HWs);
#pragma unroll
                for (int j = 0; j < 9; j++) {
                    float2 w2 = wp[c * 9 + j];
                    offs[2 * j]     += xv * w2.x;
                    offs[2 * j + 1] += xv * w2.y;
                }
            }
        }
    }

    // ---------------- Stage 2: deformable conv (32 output channels in registers) ----------------
    float acc[32];
#pragma unroll
    for (int o = 0; o < 32; o++) acc[o] = 0.0f;

#pragma unroll 1
    for (int k = 0; k < 9; k++) {
        const int ky = k / 3;
        const int kx = k - 3 * ky;
        const float py = (float)(h - 1 + ky) + offs[2 * k];       // dy = channel 2k
        const float px = (float)(w - 1 + kx) + offs[2 * k + 1];   // dx = channel 2k+1

        const float y0f = floorf(py);
        const float x0f = floorf(px);
        const float wy1 = py - y0f;
        const float wx1 = px - x0f;
        const float wy0 = 1.0f - wy1;
        const float wx0 = 1.0f - wx1;
        const float y1f = y0f + 1.0f;
        const float x1f = x0f + 1.0f;

        // Validity per reference: float-coordinate bounds check per corner.
        const bool vy0 = (y0f >= 0.0f) && (y0f <= (float)(Hn - 1));
        const bool vy1 = (y1f >= 0.0f) && (y1f <= (float)(Hn - 1));
        const bool vx0 = (x0f >= 0.0f) && (x0f <= (float)(Wn - 1));
        const bool vx1 = (x1f >= 0.0f) && (x1f <= (float)(Wn - 1));

        const float w00 = (vy0 && vx0) ? wy0 * wx0 : 0.0f;
        const float w01 = (vy0 && vx1) ? wy0 * wx1 : 0.0f;
        const float w10 = (vy1 && vx0) ? wy1 * wx0 : 0.0f;
        const float w11 = (vy1 && vx1) ? wy1 * wx1 : 0.0f;

        const int iy0 = min(max((int)y0f, 0), Hn - 1);
        const int iy1 = min(max((int)y1f, 0), Hn - 1);
        const int ix0 = min(max((int)x0f, 0), Wn - 1);
        const int ix1 = min(max((int)x1f, 0), Wn - 1);
        const int i00 = iy0 * Wn + ix0;
        const int i01 = iy0 * Wn + ix1;
        const int i10 = iy1 * Wn + ix0;
        const int i11 = iy1 * Wn + ix1;

        const float4* wp = (const float4*)(w_dcn_s + k * 32 * 32);
#pragma unroll 4
        for (int c = 0; c < CIN; c++) {
            const float* xc = xb + c * HWs;
            const float val = w00 * __ldg(xc + i00) + w01 * __ldg(xc + i01)
                            + w10 * __ldg(xc + i10) + w11 * __ldg(xc + i11);
#pragma unroll
            for (int j = 0; j < 8; j++) {
                float4 q = wp[c * 8 + j];
                acc[4 * j + 0] += val * q.x;
                acc[4 * j + 1] += val * q.y;
                acc[4 * j + 2] += val * q.z;
                acc[4 * j + 3] += val * q.w;
            }
        }
    }

    // ---------------- Epilogue: ReLU + store ----------------
    float* ob = out + (size_t)b * COUT * HWs + hw;
#pragma unroll
    for (int o = 0; o < 32; o++) {
        ob[o * HWs] = fmaxf(acc[o], 0.0f);
    }
}

extern "C" void kernel_launch(void* const* d_in, const int* in_sizes, int n_in,
                              void* d_out, int out_size)
{
    const float* x     = (const float*)d_in[0];
    const float* w_off = (const float*)d_in[1];
    const float* b_off = (const float*)d_in[2];
    const float* w_dcn = (const float*)d_in[3];
    float* out = (float*)d_out;

    const int smem_bytes = (9 * 32 * 32 + 9 * 32 * 18) * sizeof(float); // 57600 B
    cudaFuncSetAttribute(dcn_fused_kernel,
                         cudaFuncAttributeMaxDynamicSharedMemorySize, smem_bytes);

    const int total_pix = 8 * Hn * Wn;          // 204800
    const int threads = 256;
    const int blocks = total_pix / threads;     // 800
    dcn_fused_kernel<<<blocks, threads, smem_bytes>>>(x, w_off, b_off, w_dcn, out);
}